// round 15
// baseline (speedup 1.0000x reference)
#include <cuda_runtime.h>
#include <cuda_fp16.h>
#include <math.h>
#include <cstdint>

#define BATCH 8
#define SEQ 1024
#define DIM 1024
#define NH 16
#define HS 64
#define TOK (BATCH*SEQ)   // 8192
#define FFD (4*DIM)       // 4096
#define D3  (3*DIM)       // 3072

// ---------------- scratch (device globals) ---------------------------------
__device__ __half g_h[TOK*DIM];
__device__ __half g_qkv[TOK*D3];
__device__ __half g_attn[TOK*DIM];
__device__ float  g_x1[TOK*DIM];
__device__ __half g_ff[(size_t)TOK*FFD];
__device__ __half g_wqkvT[D3*DIM];
__device__ float  g_bqkv[D3];
__device__ __half g_wprojT[DIM*DIM];
__device__ __half g_w1T[FFD*DIM];
__device__ __half g_w2T[DIM*FFD];

// ======================= helpers ===========================================
__device__ __forceinline__ uint32_t smem_u32(const void* p) {
    uint32_t a;
    asm("{ .reg .u64 t; cvta.to.shared.u64 t, %1; cvt.u32.u64 %0, t; }" : "=r"(a) : "l"(p));
    return a;
}
__device__ __forceinline__ void cpa16(uint32_t dst, const void* src) {
    asm volatile("cp.async.cg.shared.global [%0], [%1], 16;\n" :: "r"(dst), "l"(src));
}
__device__ __forceinline__ void cp_commit() {
    asm volatile("cp.async.commit_group;" ::: "memory");
}
template<int N>
__device__ __forceinline__ void cp_wait() {
    asm volatile("cp.async.wait_group %0;" :: "n"(N) : "memory");
}
__device__ __forceinline__ void mma_f16(float* c, const uint32_t* a, const uint32_t* b) {
    asm volatile(
        "mma.sync.aligned.m16n8k16.row.col.f32.f16.f16.f32 "
        "{%0,%1,%2,%3}, {%4,%5,%6,%7}, {%8,%9}, {%0,%1,%2,%3};"
        : "+f"(c[0]), "+f"(c[1]), "+f"(c[2]), "+f"(c[3])
        : "r"(a[0]), "r"(a[1]), "r"(a[2]), "r"(a[3]), "r"(b[0]), "r"(b[1]));
}
__device__ __forceinline__ void ldsm4(uint32_t* r, uint32_t addr) {
    asm volatile("ldmatrix.sync.aligned.m8n8.x4.shared.b16 {%0,%1,%2,%3}, [%4];"
                 : "=r"(r[0]), "=r"(r[1]), "=r"(r[2]), "=r"(r[3]) : "r"(addr));
}
__device__ __forceinline__ void ldsm4t(uint32_t* r, uint32_t addr) {
    asm volatile("ldmatrix.sync.aligned.m8n8.x4.trans.shared.b16 {%0,%1,%2,%3}, [%4];"
                 : "=r"(r[0]), "=r"(r[1]), "=r"(r[2]), "=r"(r[3]) : "r"(addr));
}

// ======================= prep kernels ======================================
__global__ void prep_qkv(const float* __restrict__ Wq, const float* __restrict__ Wk,
                         const float* __restrict__ Wv, const float* __restrict__ bq,
                         const float* __restrict__ bk, const float* __restrict__ bv) {
    __shared__ float t[32][33];
    int h = blockIdx.z;
    int bx = blockIdx.x * 32;
    int by = blockIdx.y * 32;
    int tx = threadIdx.x;

    if (blockIdx.x == 0 && blockIdx.z == 0 && threadIdx.y == 0) {
        int i = blockIdx.y * 32 + tx;
        g_bqkv[i]         = bq[i];
        g_bqkv[i + DIM]   = bk[i];
        g_bqkv[i + 2*DIM] = bv[i];
    }

    const float* srcs[3] = {Wq, Wk, Wv};
    #pragma unroll
    for (int mtx = 0; mtx < 3; mtx++) {
        const float* iz = srcs[mtx] + (size_t)h * DIM * HS;
        __half* oz = g_wqkvT + (size_t)mtx * DIM * DIM + (size_t)h * HS * DIM;
        __syncthreads();
        #pragma unroll
        for (int i = threadIdx.y; i < 32; i += 8)
            t[i][tx] = iz[(size_t)(by + i) * HS + bx + tx];
        __syncthreads();
        #pragma unroll
        for (int i = threadIdx.y; i < 32; i += 8)
            oz[(size_t)(bx + i) * DIM + by + tx] = __float2half_rn(t[tx][i]);
    }
}

__global__ void prep_w(const float* __restrict__ Wproj, const float* __restrict__ W1,
                       const float* __restrict__ W2) {
    __shared__ float t[32][33];
    int z = blockIdx.z;
    const float* in; __half* out; int R, C;
    if (z == 0)      { in = Wproj; out = g_wprojT; R = DIM; C = DIM; }
    else if (z == 1) { in = W1;    out = g_w1T;    R = DIM; C = FFD; }
    else             { in = W2;    out = g_w2T;    R = FFD; C = DIM; }
    int bx = blockIdx.x * 32, by = blockIdx.y * 32;
    if (bx >= C || by >= R) return;
    int tx = threadIdx.x;
    #pragma unroll
    for (int i = threadIdx.y; i < 32; i += 8)
        t[i][tx] = in[(size_t)(by + i) * C + bx + tx];
    __syncthreads();
    #pragma unroll
    for (int i = threadIdx.y; i < 32; i += 8)
        out[(size_t)(bx + i) * R + by + tx] = __float2half_rn(t[tx][i]);
}

// ---------------- layernorm (fp32 in, half out) -----------------------------
__global__ void ln_kernel(const float* __restrict__ x, const float* __restrict__ g,
                          const float* __restrict__ b, __half* __restrict__ out) {
    int row = blockIdx.x;
    const float4* xr = (const float4*)(x + (size_t)row * DIM);
    float4 v = xr[threadIdx.x];
    float s  = v.x + v.y + v.z + v.w;
    float ss = v.x*v.x + v.y*v.y + v.z*v.z + v.w*v.w;
    #pragma unroll
    for (int o = 16; o; o >>= 1) {
        s  += __shfl_xor_sync(0xFFFFFFFFu, s, o);
        ss += __shfl_xor_sync(0xFFFFFFFFu, ss, o);
    }
    __shared__ float sm[8], sm2[8];
    int w = threadIdx.x >> 5, l = threadIdx.x & 31;
    if (l == 0) { sm[w] = s; sm2[w] = ss; }
    __syncthreads();
    if (w == 0) {
        s  = (l < 8) ? sm[l]  : 0.f;
        ss = (l < 8) ? sm2[l] : 0.f;
        #pragma unroll
        for (int o = 4; o; o >>= 1) {
            s  += __shfl_xor_sync(0xFFFFFFFFu, s, o);
            ss += __shfl_xor_sync(0xFFFFFFFFu, ss, o);
        }
        if (l == 0) { sm[0] = s; sm2[0] = ss; }
    }
    __syncthreads();
    float mu   = sm[0] * (1.0f / DIM);
    float var  = sm2[0] * (1.0f / DIM) - mu * mu;
    float rstd = rsqrtf(var + 1e-5f);
    float4 gg = ((const float4*)g)[threadIdx.x];
    float4 bb = ((const float4*)b)[threadIdx.x];
    __half2 h0 = __floats2half2_rn((v.x - mu) * rstd * gg.x + bb.x,
                                   (v.y - mu) * rstd * gg.y + bb.y);
    __half2 h1 = __floats2half2_rn((v.z - mu) * rstd * gg.z + bb.z,
                                   (v.w - mu) * rstd * gg.w + bb.w);
    uint2 u;
    u.x = *(uint32_t*)&h0;
    u.y = *(uint32_t*)&h1;
    *(uint2*)(out + (size_t)row * DIM + threadIdx.x * 4) = u;
}

// ======================= fp16 mma.sync GEMM (512 thr, 128x256) =============
#define KC 64
#define STRH 72
#define A_ST_H (128 * STRH)
#define B_ST_H (256 * STRH)
#define STG_H (A_ST_H + B_ST_H)
#define GSTAGES 4
#define GEMM_SMEM (GSTAGES * STG_H * 2)      // 221184 bytes

__device__ __forceinline__ void load_chunk(int tid, uint32_t as, uint32_t bs,
                                           const __half* Aj, const __half* Bj, int K) {
    #pragma unroll
    for (int t = 0; t < 2; t++) {
        int v = tid + t * 512;
        int row = v >> 3, seg = v & 7;
        cpa16(as + (row * STRH + seg * 8) * 2, Aj + (size_t)row * K + seg * 8);
    }
    #pragma unroll
    for (int t = 0; t < 4; t++) {
        int v = tid + t * 512;
        int row = v >> 3, seg = v & 7;
        cpa16(bs + (row * STRH + seg * 8) * 2, Bj + (size_t)row * K + seg * 8);
    }
}

template<int EPI>   // 0 = bias -> half, 1 = bias+res -> float, 2 = bias+leaky -> half
__global__ __launch_bounds__(512, 1)
void gemm_mma(const __half* __restrict__ A, const __half* __restrict__ Bt,
              const float* __restrict__ bias, const float* __restrict__ res,
              void* __restrict__ C, int M, int N, int K) {
    extern __shared__ __half smem[];
    uint32_t sb = smem_u32(smem);
    int tid = threadIdx.x;
    int wid = tid >> 5, lane = tid & 31;
    int grp = lane >> 2, tig = lane & 3;
    int wm = wid & 3, wn = wid >> 2;
    int bn = blockIdx.x, bm = blockIdx.y;
    int nch = K >> 6;

    uint32_t a_lane = ((lane & 15) * STRH + (lane >> 4) * 8) * 2;
    uint32_t b_lane = (((lane & 7) + ((lane >> 4) << 3)) * STRH + ((lane >> 3) & 1) * 8) * 2;

    const __half* Ag = A + (size_t)bm * 128 * K;
    const __half* Bg = Bt + (size_t)bn * 256 * K;

    #pragma unroll
    for (int j = 0; j < GSTAGES - 1; j++) {
        uint32_t st = sb + j * (STG_H * 2);
        load_chunk(tid, st, st + A_ST_H * 2, Ag + j * KC, Bg + j * KC, K);
        cp_commit();
    }

    float acc[2][8][4];
    #pragma unroll
    for (int i = 0; i < 2; i++)
        #pragma unroll
        for (int j = 0; j < 8; j++)
            #pragma unroll
            for (int q = 0; q < 4; q++) acc[i][j][q] = 0.f;

    for (int ch = 0; ch < nch; ch++) {
        int s = ch & 3;
        uint32_t asb = sb + s * (STG_H * 2);
        uint32_t bsb = asb + A_ST_H * 2;
        cp_wait<2>();
        __syncthreads();
        if (ch + 3 < nch) {
            int sw = (ch + 3) & 3;
            uint32_t st = sb + sw * (STG_H * 2);
            load_chunk(tid, st, st + A_ST_H * 2,
                       Ag + (ch + 3) * KC, Bg + (ch + 3) * KC, K);
        }
        cp_commit();
        #pragma unroll
        for (int kk = 0; kk < 4; kk++) {
            int k = kk * 16;
            uint32_t a[2][4], b[4][4];
            #pragma unroll
            for (int i = 0; i < 2; i++)
                ldsm4(a[i], asb + a_lane + (uint32_t)(((wm * 32 + i * 16) * STRH + k) * 2));
            #pragma unroll
            for (int jp = 0; jp < 4; jp++)
                ldsm4(b[jp], bsb + b_lane + (uint32_t)(((wn * 64 + jp * 16) * STRH + k) * 2));
            #pragma unroll
            for (int i = 0; i < 2; i++)
                #pragma unroll
                for (int jp = 0; jp < 4; jp++) {
                    mma_f16(acc[i][2 * jp],     a[i], &b[jp][0]);
                    mma_f16(acc[i][2 * jp + 1], a[i], &b[jp][2]);
                }
        }
    }

    #pragma unroll
    for (int i = 0; i < 2; i++) {
        int row0 = bm * 128 + wm * 32 + i * 16 + grp;
        #pragma unroll
        for (int j = 0; j < 8; j++) {
            int col = bn * 256 + wn * 64 + j * 8 + tig * 2;
            float b0 = bias[col], b1 = bias[col + 1];
            #pragma unroll
            for (int half_ = 0; half_ < 2; half_++) {
                int row = row0 + half_ * 8;
                float v0 = acc[i][j][2 * half_]     + b0;
                float v1 = acc[i][j][2 * half_ + 1] + b1;
                if (EPI == 2) {
                    v0 = v0 > 0.f ? v0 : 0.01f * v0;
                    v1 = v1 > 0.f ? v1 : 0.01f * v1;
                }
                if (EPI == 1) {
                    float2 rv = *(const float2*)(res + (size_t)row * N + col);
                    v0 += rv.x; v1 += rv.y;
                    float2 w2; w2.x = v0; w2.y = v1;
                    *(float2*)((float*)C + (size_t)row * N + col) = w2;
                } else {
                    __half2 hw = __floats2half2_rn(v0, v1);
                    *(__half2*)((__half*)C + (size_t)row * N + col) = hw;
                }
            }
        }
    }
}

// ======================= fp16 tensor-core flash attention ==================
// q-tile 128 (8 warps), key-tile 64 double-buffered, V via ldmatrix.trans.
// 2 CTAs/SM: softmax phase of one CTA overlaps MMA phase of the other.
#define PST 72
#define FA_SMEM_B (512 * PST * 2)   // 73728 B; x2 CTAs = 147456 <= 228KB

__global__ __launch_bounds__(256, 2)
void flash_attn_mma(const __half* __restrict__ qkv, __half* __restrict__ attn_out) {
    extern __shared__ __half fsh[];
    uint32_t sb = smem_u32(fsh);
    __half* Ps = fsh + 384 * PST;

    int tid = threadIdx.x;
    int wid = tid >> 5, lane = tid & 31;
    int grp = lane >> 2, tig = lane & 3;
    int bh = blockIdx.y;
    int b = bh >> 4, h = bh & 15;
    int q0 = blockIdx.x * 128;

    uint32_t a_lane = ((lane & 15) * PST + (lane >> 4) * 8) * 2;   // also V trans pattern
    uint32_t b_lane = (((lane & 7) + ((lane >> 4) << 3)) * PST + ((lane >> 3) & 1) * 8) * 2;

    const __half* qb = qkv + (size_t)(b * SEQ + q0) * D3 + h * HS;
    const __half* kb = qkv + (size_t)(b * SEQ) * D3 + DIM + h * HS;
    const __half* vb = kb + DIM;

    // prologue: Q (4/thr), K0 (2/thr), V0 (2/thr)
    #pragma unroll
    for (int t = 0; t < 4; t++) {
        int v = tid + t * 256;
        int row = v >> 3, seg = v & 7;
        cpa16(sb + (row * PST + seg * 8) * 2, qb + (size_t)row * D3 + seg * 8);
    }
    #pragma unroll
    for (int t = 0; t < 2; t++) {
        int v = tid + t * 256;
        int row = v >> 3, seg = v & 7;
        cpa16(sb + ((128 + row) * PST + seg * 8) * 2, kb + (size_t)row * D3 + seg * 8);
        cpa16(sb + ((256 + row) * PST + seg * 8) * 2, vb + (size_t)row * D3 + seg * 8);
    }
    cp_commit();

    float o[8][4];
    #pragma unroll
    for (int j = 0; j < 8; j++)
        #pragma unroll
        for (int q = 0; q < 4; q++) o[j][q] = 0.f;
    float m0 = -1e30f, m1 = -1e30f, l0 = 0.f, l1 = 0.f;

    const int NT = SEQ / 64;
    for (int kt = 0; kt < NT; kt++) {
        int pb = kt & 1, nb = pb ^ 1;
        uint32_t ks_base = sb + (128 + pb * 64) * PST * 2;
        uint32_t vs_base = sb + (256 + pb * 64) * PST * 2;
        uint32_t qs_base = sb;
        uint32_t ps_base = sb + 384 * PST * 2;

        cp_wait<0>();
        __syncthreads();   // current tile visible; all warps done with nb buffers

        if (kt + 1 < NT) {
            #pragma unroll
            for (int t = 0; t < 2; t++) {
                int v = tid + t * 256;
                int row = v >> 3, seg = v & 7;
                cpa16(sb + ((128 + nb * 64 + row) * PST + seg * 8) * 2,
                      kb + (size_t)((kt + 1) * 64 + row) * D3 + seg * 8);
                cpa16(sb + ((256 + nb * 64 + row) * PST + seg * 8) * 2,
                      vb + (size_t)((kt + 1) * 64 + row) * D3 + seg * 8);
            }
            cp_commit();
        }

        // ---- S = Q K^T ----
        float s[8][4];
        #pragma unroll
        for (int j = 0; j < 8; j++)
            #pragma unroll
            for (int q = 0; q < 4; q++) s[j][q] = 0.f;
        #pragma unroll
        for (int ks = 0; ks < 4; ks++) {
            int k = ks * 16;
            uint32_t a[4], bfr[4][4];
            ldsm4(a, qs_base + a_lane + (uint32_t)(((wid * 16) * PST + k) * 2));
            #pragma unroll
            for (int jp = 0; jp < 4; jp++)
                ldsm4(bfr[jp], ks_base + b_lane + (uint32_t)((jp * 16 * PST + k) * 2));
            #pragma unroll
            for (int jp = 0; jp < 4; jp++) {
                mma_f16(s[2 * jp],     a, &bfr[jp][0]);
                mma_f16(s[2 * jp + 1], a, &bfr[jp][2]);
            }
        }

        // ---- online softmax ----
        float mt0 = -1e30f, mt1 = -1e30f;
        #pragma unroll
        for (int j = 0; j < 8; j++) {
            s[j][0] *= 0.125f; s[j][1] *= 0.125f; s[j][2] *= 0.125f; s[j][3] *= 0.125f;
            mt0 = fmaxf(mt0, fmaxf(s[j][0], s[j][1]));
            mt1 = fmaxf(mt1, fmaxf(s[j][2], s[j][3]));
        }
        mt0 = fmaxf(mt0, __shfl_xor_sync(0xFFFFFFFFu, mt0, 1));
        mt0 = fmaxf(mt0, __shfl_xor_sync(0xFFFFFFFFu, mt0, 2));
        mt1 = fmaxf(mt1, __shfl_xor_sync(0xFFFFFFFFu, mt1, 1));
        mt1 = fmaxf(mt1, __shfl_xor_sync(0xFFFFFFFFu, mt1, 2));
        float mn0 = fmaxf(m0, mt0), mn1 = fmaxf(m1, mt1);
        float al0 = __expf(m0 - mn0), al1 = __expf(m1 - mn1);
        float lt0 = 0.f, lt1 = 0.f;
        #pragma unroll
        for (int j = 0; j < 8; j++) {
            s[j][0] = __expf(s[j][0] - mn0); s[j][1] = __expf(s[j][1] - mn0);
            s[j][2] = __expf(s[j][2] - mn1); s[j][3] = __expf(s[j][3] - mn1);
            lt0 += s[j][0] + s[j][1];
            lt1 += s[j][2] + s[j][3];
        }
        lt0 += __shfl_xor_sync(0xFFFFFFFFu, lt0, 1);
        lt0 += __shfl_xor_sync(0xFFFFFFFFu, lt0, 2);
        lt1 += __shfl_xor_sync(0xFFFFFFFFu, lt1, 1);
        lt1 += __shfl_xor_sync(0xFFFFFFFFu, lt1, 2);
        m0 = mn0; m1 = mn1;
        l0 = l0 * al0 + lt0;
        l1 = l1 * al1 + lt1;
        #pragma unroll
        for (int j = 0; j < 8; j++) {
            o[j][0] *= al0; o[j][1] *= al0; o[j][2] *= al1; o[j][3] *= al1;
        }
        #pragma unroll
        for (int j = 0; j < 8; j++) {
            *(__half2*)(Ps + (wid * 16 + grp) * PST + j * 8 + 2 * tig) =
                __floats2half2_rn(s[j][0], s[j][1]);
            *(__half2*)(Ps + (wid * 16 + grp + 8) * PST + j * 8 + 2 * tig) =
                __floats2half2_rn(s[j][2], s[j][3]);
        }
        __syncwarp();

        // ---- O += P V  (V as B-operand via ldmatrix.trans on raw [key][d]) --
        #pragma unroll
        for (int ks = 0; ks < 4; ks++) {
            int k = ks * 16;
            uint32_t a[4], bfr[4][4];
            ldsm4(a, ps_base + a_lane + (uint32_t)(((wid * 16) * PST + k) * 2));
            #pragma unroll
            for (int jp = 0; jp < 4; jp++)
                ldsm4t(bfr[jp], vs_base + a_lane + (uint32_t)((k * PST + jp * 16) * 2));
            #pragma unroll
            for (int jp = 0; jp < 4; jp++) {
                mma_f16(o[2 * jp],     a, &bfr[jp][0]);
                mma_f16(o[2 * jp + 1], a, &bfr[jp][2]);
            }
        }
    }

    // ---- epilogue ----
    float inv0 = 1.0f / l0, inv1 = 1.0f / l1;
    size_t r0 = (size_t)(b * SEQ + q0 + wid * 16 + grp);
    #pragma unroll
    for (int j = 0; j < 8; j++) {
        int col = h * HS + j * 8 + tig * 2;
        *(__half2*)(attn_out + r0 * DIM + col) =
            __floats2half2_rn(o[j][0] * inv0, o[j][1] * inv0);
        *(__half2*)(attn_out + (r0 + 8) * DIM + col) =
            __floats2half2_rn(o[j][2] * inv1, o[j][3] * inv1);
    }
}

// ---------------- host orchestration ---------------------------------------
extern "C" void kernel_launch(void* const* d_in, const int* in_sizes, int n_in,
                              void* d_out, int out_size) {
    const float* x     = (const float*)d_in[0];
    const float* Wq    = (const float*)d_in[1];
    const float* bq    = (const float*)d_in[2];
    const float* Wk    = (const float*)d_in[3];
    const float* bk    = (const float*)d_in[4];
    const float* Wv    = (const float*)d_in[5];
    const float* bv    = (const float*)d_in[6];
    const float* Wproj = (const float*)d_in[7];
    const float* bproj = (const float*)d_in[8];
    const float* W1    = (const float*)d_in[9];
    const float* b1    = (const float*)d_in[10];
    const float* W2    = (const float*)d_in[11];
    const float* b2    = (const float*)d_in[12];
    const float* ln1_g = (const float*)d_in[13];
    const float* ln1_b = (const float*)d_in[14];
    const float* ln2_g = (const float*)d_in[15];
    const float* ln2_b = (const float*)d_in[16];
    float* out = (float*)d_out;

    __half *h, *qkv, *attn, *ff, *wqkvT, *wprojT, *w1T, *w2T;
    float *x1, *bqkv;
    cudaGetSymbolAddress((void**)&h,      g_h);
    cudaGetSymbolAddress((void**)&qkv,    g_qkv);
    cudaGetSymbolAddress((void**)&attn,   g_attn);
    cudaGetSymbolAddress((void**)&x1,     g_x1);
    cudaGetSymbolAddress((void**)&ff,     g_ff);
    cudaGetSymbolAddress((void**)&wqkvT,  g_wqkvT);
    cudaGetSymbolAddress((void**)&wprojT, g_wprojT);
    cudaGetSymbolAddress((void**)&w1T,    g_w1T);
    cudaGetSymbolAddress((void**)&w2T,    g_w2T);
    cudaGetSymbolAddress((void**)&bqkv,   g_bqkv);

    cudaFuncSetAttribute(flash_attn_mma, cudaFuncAttributeMaxDynamicSharedMemorySize, FA_SMEM_B);
    cudaFuncSetAttribute(gemm_mma<0>, cudaFuncAttributeMaxDynamicSharedMemorySize, GEMM_SMEM);
    cudaFuncSetAttribute(gemm_mma<1>, cudaFuncAttributeMaxDynamicSharedMemorySize, GEMM_SMEM);
    cudaFuncSetAttribute(gemm_mma<2>, cudaFuncAttributeMaxDynamicSharedMemorySize, GEMM_SMEM);

    dim3 tb(32, 8);
    // launch 0
    prep_qkv<<<dim3(HS/32, DIM/32, NH), tb>>>(Wq, Wk, Wv, bq, bk, bv);
    // launch 1
    prep_w<<<dim3(128, 128, 3), tb>>>(Wproj, W1, W2);
    // launch 2
    ln_kernel<<<TOK, 256>>>(x, ln1_g, ln1_b, h);
    // launch 3
    gemm_mma<0><<<dim3(D3/256, TOK/128), 512, GEMM_SMEM>>>(h, wqkvT, bqkv, nullptr, qkv, TOK, D3, DIM);
    // launch 4
    flash_attn_mma<<<dim3(SEQ/128, BATCH*NH), 256, FA_SMEM_B>>>(qkv, attn);
    // launch 5
    gemm_mma<1><<<dim3(DIM/256, TOK/128), 512, GEMM_SMEM>>>(attn, wprojT, bproj, x, x1, TOK, DIM, DIM);
    // launch 6
    ln_kernel<<<TOK, 256>>>(x1, ln2_g, ln2_b, h);
    // launch 7
    gemm_mma<2><<<dim3(FFD/256, TOK/128), 512, GEMM_SMEM>>>(h, w1T, b1, nullptr, ff, TOK, FFD, DIM);
    // launch 8
    gemm_mma<1><<<dim3(DIM/256, TOK/128), 512, GEMM_SMEM>>>(ff, w2T, b2, x1, out, TOK, DIM, FFD);
}

// round 16
// speedup vs baseline: 1.0066x; 1.0066x over previous
#include <cuda_runtime.h>
#include <cuda_fp16.h>
#include <math.h>
#include <cstdint>

#define BATCH 8
#define SEQ 1024
#define DIM 1024
#define NH 16
#define HS 64
#define TOK (BATCH*SEQ)   // 8192
#define FFD (4*DIM)       // 4096
#define D3  (3*DIM)       // 3072

// ---------------- scratch (device globals) ---------------------------------
__device__ __half g_h[TOK*DIM];
__device__ __half g_qkv[TOK*D3];
__device__ __half g_attn[TOK*DIM];
__device__ float  g_x1[TOK*DIM];
__device__ __half g_ff[(size_t)TOK*FFD];
__device__ __half g_wqkvT[D3*DIM];
__device__ float  g_bqkv[D3];
__device__ __half g_wprojT[DIM*DIM];
__device__ __half g_w1T[FFD*DIM];
__device__ __half g_w2T[DIM*FFD];

// ======================= helpers ===========================================
__device__ __forceinline__ uint32_t smem_u32(const void* p) {
    uint32_t a;
    asm("{ .reg .u64 t; cvta.to.shared.u64 t, %1; cvt.u32.u64 %0, t; }" : "=r"(a) : "l"(p));
    return a;
}
__device__ __forceinline__ void cpa16(uint32_t dst, const void* src) {
    asm volatile("cp.async.cg.shared.global [%0], [%1], 16;\n" :: "r"(dst), "l"(src));
}
__device__ __forceinline__ void cp_commit() {
    asm volatile("cp.async.commit_group;" ::: "memory");
}
template<int N>
__device__ __forceinline__ void cp_wait() {
    asm volatile("cp.async.wait_group %0;" :: "n"(N) : "memory");
}
__device__ __forceinline__ void mma_f16(float* c, const uint32_t* a, const uint32_t* b) {
    asm volatile(
        "mma.sync.aligned.m16n8k16.row.col.f32.f16.f16.f32 "
        "{%0,%1,%2,%3}, {%4,%5,%6,%7}, {%8,%9}, {%0,%1,%2,%3};"
        : "+f"(c[0]), "+f"(c[1]), "+f"(c[2]), "+f"(c[3])
        : "r"(a[0]), "r"(a[1]), "r"(a[2]), "r"(a[3]), "r"(b[0]), "r"(b[1]));
}
__device__ __forceinline__ void ldsm4(uint32_t* r, uint32_t addr) {
    asm volatile("ldmatrix.sync.aligned.m8n8.x4.shared.b16 {%0,%1,%2,%3}, [%4];"
                 : "=r"(r[0]), "=r"(r[1]), "=r"(r[2]), "=r"(r[3]) : "r"(addr));
}
__device__ __forceinline__ void ldsm4t(uint32_t* r, uint32_t addr) {
    asm volatile("ldmatrix.sync.aligned.m8n8.x4.trans.shared.b16 {%0,%1,%2,%3}, [%4];"
                 : "=r"(r[0]), "=r"(r[1]), "=r"(r[2]), "=r"(r[3]) : "r"(addr));
}

// ======================= prep kernels ======================================
__global__ void prep_qkv(const float* __restrict__ Wq, const float* __restrict__ Wk,
                         const float* __restrict__ Wv, const float* __restrict__ bq,
                         const float* __restrict__ bk, const float* __restrict__ bv) {
    __shared__ float t[32][33];
    int h = blockIdx.z;
    int bx = blockIdx.x * 32;
    int by = blockIdx.y * 32;
    int tx = threadIdx.x;

    if (blockIdx.x == 0 && blockIdx.z == 0 && threadIdx.y == 0) {
        int i = blockIdx.y * 32 + tx;
        g_bqkv[i]         = bq[i];
        g_bqkv[i + DIM]   = bk[i];
        g_bqkv[i + 2*DIM] = bv[i];
    }

    const float* srcs[3] = {Wq, Wk, Wv};
    #pragma unroll
    for (int mtx = 0; mtx < 3; mtx++) {
        const float* iz = srcs[mtx] + (size_t)h * DIM * HS;
        __half* oz = g_wqkvT + (size_t)mtx * DIM * DIM + (size_t)h * HS * DIM;
        __syncthreads();
        #pragma unroll
        for (int i = threadIdx.y; i < 32; i += 8)
            t[i][tx] = iz[(size_t)(by + i) * HS + bx + tx];
        __syncthreads();
        #pragma unroll
        for (int i = threadIdx.y; i < 32; i += 8)
            oz[(size_t)(bx + i) * DIM + by + tx] = __float2half_rn(t[tx][i]);
    }
}

__global__ void prep_w(const float* __restrict__ Wproj, const float* __restrict__ W1,
                       const float* __restrict__ W2) {
    __shared__ float t[32][33];
    int z = blockIdx.z;
    const float* in; __half* out; int R, C;
    if (z == 0)      { in = Wproj; out = g_wprojT; R = DIM; C = DIM; }
    else if (z == 1) { in = W1;    out = g_w1T;    R = DIM; C = FFD; }
    else             { in = W2;    out = g_w2T;    R = FFD; C = DIM; }
    int bx = blockIdx.x * 32, by = blockIdx.y * 32;
    if (bx >= C || by >= R) return;
    int tx = threadIdx.x;
    #pragma unroll
    for (int i = threadIdx.y; i < 32; i += 8)
        t[i][tx] = in[(size_t)(by + i) * C + bx + tx];
    __syncthreads();
    #pragma unroll
    for (int i = threadIdx.y; i < 32; i += 8)
        out[(size_t)(bx + i) * R + by + tx] = __float2half_rn(t[tx][i]);
}

// ---------------- layernorm: 2 rows per 256-thread block --------------------
__global__ void ln_kernel(const float* __restrict__ x, const float* __restrict__ g,
                          const float* __restrict__ b, __half* __restrict__ out) {
    __shared__ float sm[8], sm2[8];
    int w = threadIdx.x >> 5, l = threadIdx.x & 31;
    float4 gg = ((const float4*)g)[threadIdx.x];
    float4 bb = ((const float4*)b)[threadIdx.x];

    #pragma unroll
    for (int rr = 0; rr < 2; rr++) {
        int row = blockIdx.x * 2 + rr;
        if (rr) __syncthreads();   // protect sm reuse across rows
        float4 v = ((const float4*)(x + (size_t)row * DIM))[threadIdx.x];
        float s  = v.x + v.y + v.z + v.w;
        float ss = v.x*v.x + v.y*v.y + v.z*v.z + v.w*v.w;
        #pragma unroll
        for (int o = 16; o; o >>= 1) {
            s  += __shfl_xor_sync(0xFFFFFFFFu, s, o);
            ss += __shfl_xor_sync(0xFFFFFFFFu, ss, o);
        }
        if (l == 0) { sm[w] = s; sm2[w] = ss; }
        __syncthreads();
        if (w == 0) {
            s  = (l < 8) ? sm[l]  : 0.f;
            ss = (l < 8) ? sm2[l] : 0.f;
            #pragma unroll
            for (int o = 4; o; o >>= 1) {
                s  += __shfl_xor_sync(0xFFFFFFFFu, s, o);
                ss += __shfl_xor_sync(0xFFFFFFFFu, ss, o);
            }
            if (l == 0) { sm[0] = s; sm2[0] = ss; }
        }
        __syncthreads();
        float mu   = sm[0] * (1.0f / DIM);
        float var  = sm2[0] * (1.0f / DIM) - mu * mu;
        float rstd = rsqrtf(var + 1e-5f);
        __half2 h0 = __floats2half2_rn((v.x - mu) * rstd * gg.x + bb.x,
                                       (v.y - mu) * rstd * gg.y + bb.y);
        __half2 h1 = __floats2half2_rn((v.z - mu) * rstd * gg.z + bb.z,
                                       (v.w - mu) * rstd * gg.w + bb.w);
        uint2 u;
        u.x = *(uint32_t*)&h0;
        u.y = *(uint32_t*)&h1;
        *(uint2*)(out + (size_t)row * DIM + threadIdx.x * 4) = u;
    }
}

// ======================= fp16 mma.sync GEMM (512 thr, 128x256) =============
#define KC 64
#define STRH 72
#define A_ST_H (128 * STRH)
#define B_ST_H (256 * STRH)
#define STG_H (A_ST_H + B_ST_H)
#define GSTAGES 4
#define GEMM_SMEM (GSTAGES * STG_H * 2)      // 221184 bytes

__device__ __forceinline__ void load_chunk(int tid, uint32_t as, uint32_t bs,
                                           const __half* Aj, const __half* Bj, int K) {
    #pragma unroll
    for (int t = 0; t < 2; t++) {
        int v = tid + t * 512;
        int row = v >> 3, seg = v & 7;
        cpa16(as + (row * STRH + seg * 8) * 2, Aj + (size_t)row * K + seg * 8);
    }
    #pragma unroll
    for (int t = 0; t < 4; t++) {
        int v = tid + t * 512;
        int row = v >> 3, seg = v & 7;
        cpa16(bs + (row * STRH + seg * 8) * 2, Bj + (size_t)row * K + seg * 8);
    }
}

template<int EPI>   // 0 = bias -> half, 1 = bias+res -> float, 2 = bias+leaky -> half
__global__ __launch_bounds__(512, 1)
void gemm_mma(const __half* __restrict__ A, const __half* __restrict__ Bt,
              const float* __restrict__ bias, const float* __restrict__ res,
              void* __restrict__ C, int M, int N, int K) {
    extern __shared__ __half smem[];
    uint32_t sb = smem_u32(smem);
    int tid = threadIdx.x;
    int wid = tid >> 5, lane = tid & 31;
    int grp = lane >> 2, tig = lane & 3;
    int wm = wid & 3, wn = wid >> 2;
    int bn = blockIdx.x, bm = blockIdx.y;
    int nch = K >> 6;

    uint32_t a_lane = ((lane & 15) * STRH + (lane >> 4) * 8) * 2;
    uint32_t b_lane = (((lane & 7) + ((lane >> 4) << 3)) * STRH + ((lane >> 3) & 1) * 8) * 2;

    const __half* Ag = A + (size_t)bm * 128 * K;
    const __half* Bg = Bt + (size_t)bn * 256 * K;

    #pragma unroll
    for (int j = 0; j < GSTAGES - 1; j++) {
        uint32_t st = sb + j * (STG_H * 2);
        load_chunk(tid, st, st + A_ST_H * 2, Ag + j * KC, Bg + j * KC, K);
        cp_commit();
    }

    float acc[2][8][4];
    #pragma unroll
    for (int i = 0; i < 2; i++)
        #pragma unroll
        for (int j = 0; j < 8; j++)
            #pragma unroll
            for (int q = 0; q < 4; q++) acc[i][j][q] = 0.f;

    for (int ch = 0; ch < nch; ch++) {
        int s = ch & 3;
        uint32_t asb = sb + s * (STG_H * 2);
        uint32_t bsb = asb + A_ST_H * 2;
        cp_wait<2>();
        __syncthreads();
        if (ch + 3 < nch) {
            int sw = (ch + 3) & 3;
            uint32_t st = sb + sw * (STG_H * 2);
            load_chunk(tid, st, st + A_ST_H * 2,
                       Ag + (ch + 3) * KC, Bg + (ch + 3) * KC, K);
        }
        cp_commit();
        #pragma unroll
        for (int kk = 0; kk < 4; kk++) {
            int k = kk * 16;
            uint32_t a[2][4], b[4][4];
            #pragma unroll
            for (int i = 0; i < 2; i++)
                ldsm4(a[i], asb + a_lane + (uint32_t)(((wm * 32 + i * 16) * STRH + k) * 2));
            #pragma unroll
            for (int jp = 0; jp < 4; jp++)
                ldsm4(b[jp], bsb + b_lane + (uint32_t)(((wn * 64 + jp * 16) * STRH + k) * 2));
            #pragma unroll
            for (int i = 0; i < 2; i++)
                #pragma unroll
                for (int jp = 0; jp < 4; jp++) {
                    mma_f16(acc[i][2 * jp],     a[i], &b[jp][0]);
                    mma_f16(acc[i][2 * jp + 1], a[i], &b[jp][2]);
                }
        }
    }

    #pragma unroll
    for (int i = 0; i < 2; i++) {
        int row0 = bm * 128 + wm * 32 + i * 16 + grp;
        #pragma unroll
        for (int j = 0; j < 8; j++) {
            int col = bn * 256 + wn * 64 + j * 8 + tig * 2;
            float b0 = bias[col], b1 = bias[col + 1];
            #pragma unroll
            for (int half_ = 0; half_ < 2; half_++) {
                int row = row0 + half_ * 8;
                float v0 = acc[i][j][2 * half_]     + b0;
                float v1 = acc[i][j][2 * half_ + 1] + b1;
                if (EPI == 2) {
                    v0 = v0 > 0.f ? v0 : 0.01f * v0;
                    v1 = v1 > 0.f ? v1 : 0.01f * v1;
                }
                if (EPI == 1) {
                    float2 rv = *(const float2*)(res + (size_t)row * N + col);
                    v0 += rv.x; v1 += rv.y;
                    float2 w2; w2.x = v0; w2.y = v1;
                    *(float2*)((float*)C + (size_t)row * N + col) = w2;
                } else {
                    __half2 hw = __floats2half2_rn(v0, v1);
                    *(__half2*)((__half*)C + (size_t)row * N + col) = hw;
                }
            }
        }
    }
}

// ======================= fp16 tensor-core flash attention ==================
// q-tile 128 (8 warps), key-tile 64 double-buffered, V via ldmatrix.trans.
#define PST 72
#define FA_SMEM_B (512 * PST * 2)

__global__ __launch_bounds__(256)
void flash_attn_mma(const __half* __restrict__ qkv, __half* __restrict__ attn_out) {
    extern __shared__ __half fsh[];
    uint32_t sb = smem_u32(fsh);
    __half* Ps = fsh + 384 * PST;

    int tid = threadIdx.x;
    int wid = tid >> 5, lane = tid & 31;
    int grp = lane >> 2, tig = lane & 3;
    int bh = blockIdx.y;
    int b = bh >> 4, h = bh & 15;
    int q0 = blockIdx.x * 128;

    uint32_t a_lane = ((lane & 15) * PST + (lane >> 4) * 8) * 2;
    uint32_t b_lane = (((lane & 7) + ((lane >> 4) << 3)) * PST + ((lane >> 3) & 1) * 8) * 2;

    const __half* qb = qkv + (size_t)(b * SEQ + q0) * D3 + h * HS;
    const __half* kb = qkv + (size_t)(b * SEQ) * D3 + DIM + h * HS;
    const __half* vb = kb + DIM;

    #pragma unroll
    for (int t = 0; t < 4; t++) {
        int v = tid + t * 256;
        int row = v >> 3, seg = v & 7;
        cpa16(sb + (row * PST + seg * 8) * 2, qb + (size_t)row * D3 + seg * 8);
    }
    #pragma unroll
    for (int t = 0; t < 2; t++) {
        int v = tid + t * 256;
        int row = v >> 3, seg = v & 7;
        cpa16(sb + ((128 + row) * PST + seg * 8) * 2, kb + (size_t)row * D3 + seg * 8);
        cpa16(sb + ((256 + row) * PST + seg * 8) * 2, vb + (size_t)row * D3 + seg * 8);
    }
    cp_commit();

    float o[8][4];
    #pragma unroll
    for (int j = 0; j < 8; j++)
        #pragma unroll
        for (int q = 0; q < 4; q++) o[j][q] = 0.f;
    float m0 = -1e30f, m1 = -1e30f, l0 = 0.f, l1 = 0.f;

    const int NT = SEQ / 64;
    for (int kt = 0; kt < NT; kt++) {
        int pb = kt & 1, nb = pb ^ 1;
        uint32_t ks_base = sb + (128 + pb * 64) * PST * 2;
        uint32_t vs_base = sb + (256 + pb * 64) * PST * 2;
        uint32_t qs_base = sb;
        uint32_t ps_base = sb + 384 * PST * 2;

        cp_wait<0>();
        __syncthreads();

        if (kt + 1 < NT) {
            #pragma unroll
            for (int t = 0; t < 2; t++) {
                int v = tid + t * 256;
                int row = v >> 3, seg = v & 7;
                cpa16(sb + ((128 + nb * 64 + row) * PST + seg * 8) * 2,
                      kb + (size_t)((kt + 1) * 64 + row) * D3 + seg * 8);
                cpa16(sb + ((256 + nb * 64 + row) * PST + seg * 8) * 2,
                      vb + (size_t)((kt + 1) * 64 + row) * D3 + seg * 8);
            }
            cp_commit();
        }

        // ---- S = Q K^T ----
        float s[8][4];
        #pragma unroll
        for (int j = 0; j < 8; j++)
            #pragma unroll
            for (int q = 0; q < 4; q++) s[j][q] = 0.f;
        #pragma unroll
        for (int ks = 0; ks < 4; ks++) {
            int k = ks * 16;
            uint32_t a[4], bfr[4][4];
            ldsm4(a, qs_base + a_lane + (uint32_t)(((wid * 16) * PST + k) * 2));
            #pragma unroll
            for (int jp = 0; jp < 4; jp++)
                ldsm4(bfr[jp], ks_base + b_lane + (uint32_t)((jp * 16 * PST + k) * 2));
            #pragma unroll
            for (int jp = 0; jp < 4; jp++) {
                mma_f16(s[2 * jp],     a, &bfr[jp][0]);
                mma_f16(s[2 * jp + 1], a, &bfr[jp][2]);
            }
        }

        // ---- online softmax ----
        float mt0 = -1e30f, mt1 = -1e30f;
        #pragma unroll
        for (int j = 0; j < 8; j++) {
            s[j][0] *= 0.125f; s[j][1] *= 0.125f; s[j][2] *= 0.125f; s[j][3] *= 0.125f;
            mt0 = fmaxf(mt0, fmaxf(s[j][0], s[j][1]));
            mt1 = fmaxf(mt1, fmaxf(s[j][2], s[j][3]));
        }
        mt0 = fmaxf(mt0, __shfl_xor_sync(0xFFFFFFFFu, mt0, 1));
        mt0 = fmaxf(mt0, __shfl_xor_sync(0xFFFFFFFFu, mt0, 2));
        mt1 = fmaxf(mt1, __shfl_xor_sync(0xFFFFFFFFu, mt1, 1));
        mt1 = fmaxf(mt1, __shfl_xor_sync(0xFFFFFFFFu, mt1, 2));
        float mn0 = fmaxf(m0, mt0), mn1 = fmaxf(m1, mt1);
        float al0 = __expf(m0 - mn0), al1 = __expf(m1 - mn1);
        float lt0 = 0.f, lt1 = 0.f;
        #pragma unroll
        for (int j = 0; j < 8; j++) {
            s[j][0] = __expf(s[j][0] - mn0); s[j][1] = __expf(s[j][1] - mn0);
            s[j][2] = __expf(s[j][2] - mn1); s[j][3] = __expf(s[j][3] - mn1);
            lt0 += s[j][0] + s[j][1];
            lt1 += s[j][2] + s[j][3];
        }
        lt0 += __shfl_xor_sync(0xFFFFFFFFu, lt0, 1);
        lt0 += __shfl_xor_sync(0xFFFFFFFFu, lt0, 2);
        lt1 += __shfl_xor_sync(0xFFFFFFFFu, lt1, 1);
        lt1 += __shfl_xor_sync(0xFFFFFFFFu, lt1, 2);
        m0 = mn0; m1 = mn1;
        l0 = l0 * al0 + lt0;
        l1 = l1 * al1 + lt1;
        #pragma unroll
        for (int j = 0; j < 8; j++) {
            o[j][0] *= al0; o[j][1] *= al0; o[j][2] *= al1; o[j][3] *= al1;
        }
        #pragma unroll
        for (int j = 0; j < 8; j++) {
            *(__half2*)(Ps + (wid * 16 + grp) * PST + j * 8 + 2 * tig) =
                __floats2half2_rn(s[j][0], s[j][1]);
            *(__half2*)(Ps + (wid * 16 + grp + 8) * PST + j * 8 + 2 * tig) =
                __floats2half2_rn(s[j][2], s[j][3]);
        }
        __syncwarp();

        // ---- O += P V ----
        #pragma unroll
        for (int ks = 0; ks < 4; ks++) {
            int k = ks * 16;
            uint32_t a[4], bfr[4][4];
            ldsm4(a, ps_base + a_lane + (uint32_t)(((wid * 16) * PST + k) * 2));
            #pragma unroll
            for (int jp = 0; jp < 4; jp++)
                ldsm4t(bfr[jp], vs_base + a_lane + (uint32_t)((k * PST + jp * 16) * 2));
            #pragma unroll
            for (int jp = 0; jp < 4; jp++) {
                mma_f16(o[2 * jp],     a, &bfr[jp][0]);
                mma_f16(o[2 * jp + 1], a, &bfr[jp][2]);
            }
        }
    }

    // ---- epilogue ----
    float inv0 = 1.0f / l0, inv1 = 1.0f / l1;
    size_t r0 = (size_t)(b * SEQ + q0 + wid * 16 + grp);
    #pragma unroll
    for (int j = 0; j < 8; j++) {
        int col = h * HS + j * 8 + tig * 2;
        *(__half2*)(attn_out + r0 * DIM + col) =
            __floats2half2_rn(o[j][0] * inv0, o[j][1] * inv0);
        *(__half2*)(attn_out + (r0 + 8) * DIM + col) =
            __floats2half2_rn(o[j][2] * inv1, o[j][3] * inv1);
    }
}

// ---------------- host orchestration ---------------------------------------
extern "C" void kernel_launch(void* const* d_in, const int* in_sizes, int n_in,
                              void* d_out, int out_size) {
    const float* x     = (const float*)d_in[0];
    const float* Wq    = (const float*)d_in[1];
    const float* bq    = (const float*)d_in[2];
    const float* Wk    = (const float*)d_in[3];
    const float* bk    = (const float*)d_in[4];
    const float* Wv    = (const float*)d_in[5];
    const float* bv    = (const float*)d_in[6];
    const float* Wproj = (const float*)d_in[7];
    const float* bproj = (const float*)d_in[8];
    const float* W1    = (const float*)d_in[9];
    const float* b1    = (const float*)d_in[10];
    const float* W2    = (const float*)d_in[11];
    const float* b2    = (const float*)d_in[12];
    const float* ln1_g = (const float*)d_in[13];
    const float* ln1_b = (const float*)d_in[14];
    const float* ln2_g = (const float*)d_in[15];
    const float* ln2_b = (const float*)d_in[16];
    float* out = (float*)d_out;

    __half *h, *qkv, *attn, *ff, *wqkvT, *wprojT, *w1T, *w2T;
    float *x1, *bqkv;
    cudaGetSymbolAddress((void**)&h,      g_h);
    cudaGetSymbolAddress((void**)&qkv,    g_qkv);
    cudaGetSymbolAddress((void**)&attn,   g_attn);
    cudaGetSymbolAddress((void**)&x1,     g_x1);
    cudaGetSymbolAddress((void**)&ff,     g_ff);
    cudaGetSymbolAddress((void**)&wqkvT,  g_wqkvT);
    cudaGetSymbolAddress((void**)&wprojT, g_wprojT);
    cudaGetSymbolAddress((void**)&w1T,    g_w1T);
    cudaGetSymbolAddress((void**)&w2T,    g_w2T);
    cudaGetSymbolAddress((void**)&bqkv,   g_bqkv);

    cudaFuncSetAttribute(flash_attn_mma, cudaFuncAttributeMaxDynamicSharedMemorySize, FA_SMEM_B);
    cudaFuncSetAttribute(gemm_mma<0>, cudaFuncAttributeMaxDynamicSharedMemorySize, GEMM_SMEM);
    cudaFuncSetAttribute(gemm_mma<1>, cudaFuncAttributeMaxDynamicSharedMemorySize, GEMM_SMEM);
    cudaFuncSetAttribute(gemm_mma<2>, cudaFuncAttributeMaxDynamicSharedMemorySize, GEMM_SMEM);

    dim3 tb(32, 8);
    // launch 0
    prep_qkv<<<dim3(HS/32, DIM/32, NH), tb>>>(Wq, Wk, Wv, bq, bk, bv);
    // launch 1
    prep_w<<<dim3(128, 128, 3), tb>>>(Wproj, W1, W2);
    // launch 2
    ln_kernel<<<TOK/2, 256>>>(x, ln1_g, ln1_b, h);
    // launch 3
    gemm_mma<0><<<dim3(D3/256, TOK/128), 512, GEMM_SMEM>>>(h, wqkvT, bqkv, nullptr, qkv, TOK, D3, DIM);
    // launch 4
    flash_attn_mma<<<dim3(SEQ/128, BATCH*NH), 256, FA_SMEM_B>>>(qkv, attn);
    // launch 5
    gemm_mma<1><<<dim3(DIM/256, TOK/128), 512, GEMM_SMEM>>>(attn, wprojT, bproj, x, x1, TOK, DIM, DIM);
    // launch 6
    ln_kernel<<<TOK/2, 256>>>(x1, ln2_g, ln2_b, h);
    // launch 7
    gemm_mma<2><<<dim3(FFD/256, TOK/128), 512, GEMM_SMEM>>>(h, w1T, b1, nullptr, ff, TOK, FFD, DIM);
    // launch 8
    gemm_mma<1><<<dim3(DIM/256, TOK/128), 512, GEMM_SMEM>>>(ff, w2T, b2, x1, out, TOK, DIM, FFD);
}

// round 17
// speedup vs baseline: 1.0152x; 1.0085x over previous
#include <cuda_runtime.h>
#include <cuda_fp16.h>
#include <math.h>
#include <cstdint>

#define BATCH 8
#define SEQ 1024
#define DIM 1024
#define NH 16
#define HS 64
#define TOK (BATCH*SEQ)   // 8192
#define FFD (4*DIM)       // 4096
#define D3  (3*DIM)       // 3072

// ---------------- scratch (device globals) ---------------------------------
__device__ __half g_h[TOK*DIM];
__device__ __half g_qkv[TOK*D3];
__device__ __half g_attn[TOK*DIM];
__device__ float  g_x1[TOK*DIM];
__device__ __half g_ff[(size_t)TOK*FFD];
__device__ __half g_wqkvT[D3*DIM];
__device__ float  g_bqkv[D3];
__device__ __half g_wprojT[DIM*DIM];
__device__ __half g_w1T[FFD*DIM];
__device__ __half g_w2T[DIM*FFD];

// ======================= helpers ===========================================
__device__ __forceinline__ uint32_t smem_u32(const void* p) {
    uint32_t a;
    asm("{ .reg .u64 t; cvta.to.shared.u64 t, %1; cvt.u32.u64 %0, t; }" : "=r"(a) : "l"(p));
    return a;
}
__device__ __forceinline__ void cpa16(uint32_t dst, const void* src) {
    asm volatile("cp.async.cg.shared.global [%0], [%1], 16;\n" :: "r"(dst), "l"(src));
}
__device__ __forceinline__ void cp_commit() {
    asm volatile("cp.async.commit_group;" ::: "memory");
}
template<int N>
__device__ __forceinline__ void cp_wait() {
    asm volatile("cp.async.wait_group %0;" :: "n"(N) : "memory");
}
__device__ __forceinline__ void mma_f16(float* c, const uint32_t* a, const uint32_t* b) {
    asm volatile(
        "mma.sync.aligned.m16n8k16.row.col.f32.f16.f16.f32 "
        "{%0,%1,%2,%3}, {%4,%5,%6,%7}, {%8,%9}, {%0,%1,%2,%3};"
        : "+f"(c[0]), "+f"(c[1]), "+f"(c[2]), "+f"(c[3])
        : "r"(a[0]), "r"(a[1]), "r"(a[2]), "r"(a[3]), "r"(b[0]), "r"(b[1]));
}
__device__ __forceinline__ void ldsm4(uint32_t* r, uint32_t addr) {
    asm volatile("ldmatrix.sync.aligned.m8n8.x4.shared.b16 {%0,%1,%2,%3}, [%4];"
                 : "=r"(r[0]), "=r"(r[1]), "=r"(r[2]), "=r"(r[3]) : "r"(addr));
}
__device__ __forceinline__ void ldsm4t(uint32_t* r, uint32_t addr) {
    asm volatile("ldmatrix.sync.aligned.m8n8.x4.trans.shared.b16 {%0,%1,%2,%3}, [%4];"
                 : "=r"(r[0]), "=r"(r[1]), "=r"(r[2]), "=r"(r[3]) : "r"(addr));
}

// ======================= prep kernels ======================================
__global__ void prep_qkv(const float* __restrict__ Wq, const float* __restrict__ Wk,
                         const float* __restrict__ Wv, const float* __restrict__ bq,
                         const float* __restrict__ bk, const float* __restrict__ bv) {
    __shared__ float t[32][33];
    int h = blockIdx.z;
    int bx = blockIdx.x * 32;
    int by = blockIdx.y * 32;
    int tx = threadIdx.x;

    if (blockIdx.x == 0 && blockIdx.z == 0 && threadIdx.y == 0) {
        int i = blockIdx.y * 32 + tx;
        g_bqkv[i]         = bq[i];
        g_bqkv[i + DIM]   = bk[i];
        g_bqkv[i + 2*DIM] = bv[i];
    }

    const float* srcs[3] = {Wq, Wk, Wv};
    #pragma unroll
    for (int mtx = 0; mtx < 3; mtx++) {
        const float* iz = srcs[mtx] + (size_t)h * DIM * HS;
        __half* oz = g_wqkvT + (size_t)mtx * DIM * DIM + (size_t)h * HS * DIM;
        __syncthreads();
        #pragma unroll
        for (int i = threadIdx.y; i < 32; i += 8)
            t[i][tx] = iz[(size_t)(by + i) * HS + bx + tx];
        __syncthreads();
        #pragma unroll
        for (int i = threadIdx.y; i < 32; i += 8)
            oz[(size_t)(bx + i) * DIM + by + tx] = __float2half_rn(t[tx][i]);
    }
}

__global__ void prep_w(const float* __restrict__ Wproj, const float* __restrict__ W1,
                       const float* __restrict__ W2) {
    __shared__ float t[32][33];
    int z = blockIdx.z;
    const float* in; __half* out; int R, C;
    if (z == 0)      { in = Wproj; out = g_wprojT; R = DIM; C = DIM; }
    else if (z == 1) { in = W1;    out = g_w1T;    R = DIM; C = FFD; }
    else             { in = W2;    out = g_w2T;    R = FFD; C = DIM; }
    int bx = blockIdx.x * 32, by = blockIdx.y * 32;
    if (bx >= C || by >= R) return;
    int tx = threadIdx.x;
    #pragma unroll
    for (int i = threadIdx.y; i < 32; i += 8)
        t[i][tx] = in[(size_t)(by + i) * C + bx + tx];
    __syncthreads();
    #pragma unroll
    for (int i = threadIdx.y; i < 32; i += 8)
        out[(size_t)(bx + i) * R + by + tx] = __float2half_rn(t[tx][i]);
}

// ---------------- layernorm: 2 rows per 256-thread block --------------------
__global__ void ln_kernel(const float* __restrict__ x, const float* __restrict__ g,
                          const float* __restrict__ b, __half* __restrict__ out) {
    __shared__ float sm[8], sm2[8];
    int w = threadIdx.x >> 5, l = threadIdx.x & 31;
    float4 gg = ((const float4*)g)[threadIdx.x];
    float4 bb = ((const float4*)b)[threadIdx.x];

    #pragma unroll
    for (int rr = 0; rr < 2; rr++) {
        int row = blockIdx.x * 2 + rr;
        if (rr) __syncthreads();
        float4 v = ((const float4*)(x + (size_t)row * DIM))[threadIdx.x];
        float s  = v.x + v.y + v.z + v.w;
        float ss = v.x*v.x + v.y*v.y + v.z*v.z + v.w*v.w;
        #pragma unroll
        for (int o = 16; o; o >>= 1) {
            s  += __shfl_xor_sync(0xFFFFFFFFu, s, o);
            ss += __shfl_xor_sync(0xFFFFFFFFu, ss, o);
        }
        if (l == 0) { sm[w] = s; sm2[w] = ss; }
        __syncthreads();
        if (w == 0) {
            s  = (l < 8) ? sm[l]  : 0.f;
            ss = (l < 8) ? sm2[l] : 0.f;
            #pragma unroll
            for (int o = 4; o; o >>= 1) {
                s  += __shfl_xor_sync(0xFFFFFFFFu, s, o);
                ss += __shfl_xor_sync(0xFFFFFFFFu, ss, o);
            }
            if (l == 0) { sm[0] = s; sm2[0] = ss; }
        }
        __syncthreads();
        float mu   = sm[0] * (1.0f / DIM);
        float var  = sm2[0] * (1.0f / DIM) - mu * mu;
        float rstd = rsqrtf(var + 1e-5f);
        __half2 h0 = __floats2half2_rn((v.x - mu) * rstd * gg.x + bb.x,
                                       (v.y - mu) * rstd * gg.y + bb.y);
        __half2 h1 = __floats2half2_rn((v.z - mu) * rstd * gg.z + bb.z,
                                       (v.w - mu) * rstd * gg.w + bb.w);
        uint2 u;
        u.x = *(uint32_t*)&h0;
        u.y = *(uint32_t*)&h1;
        *(uint2*)(out + (size_t)row * DIM + threadIdx.x * 4) = u;
    }
}

// ======================= fp16 mma.sync GEMM (512 thr, 128x256) =============
#define KC 64
#define STRH 72
#define A_ST_H (128 * STRH)
#define B_ST_H (256 * STRH)
#define STG_H (A_ST_H + B_ST_H)
#define GSTAGES 4
#define GEMM_SMEM (GSTAGES * STG_H * 2)      // 221184 bytes

__device__ __forceinline__ void load_chunk(int tid, uint32_t as, uint32_t bs,
                                           const __half* Aj, const __half* Bj, int K) {
    #pragma unroll
    for (int t = 0; t < 2; t++) {
        int v = tid + t * 512;
        int row = v >> 3, seg = v & 7;
        cpa16(as + (row * STRH + seg * 8) * 2, Aj + (size_t)row * K + seg * 8);
    }
    #pragma unroll
    for (int t = 0; t < 4; t++) {
        int v = tid + t * 512;
        int row = v >> 3, seg = v & 7;
        cpa16(bs + (row * STRH + seg * 8) * 2, Bj + (size_t)row * K + seg * 8);
    }
}

template<int EPI>   // 0 = bias -> half, 1 = bias+res -> float, 2 = bias+leaky -> half
__global__ __launch_bounds__(512, 1)
void gemm_mma(const __half* __restrict__ A, const __half* __restrict__ Bt,
              const float* __restrict__ bias, const float* __restrict__ res,
              void* __restrict__ C, int M, int N, int K) {
    extern __shared__ __half smem[];
    uint32_t sb = smem_u32(smem);
    int tid = threadIdx.x;
    int wid = tid >> 5, lane = tid & 31;
    int grp = lane >> 2, tig = lane & 3;
    int wm = wid & 3, wn = wid >> 2;
    int bn = blockIdx.x, bm = blockIdx.y;
    int nch = K >> 6;

    uint32_t a_lane = ((lane & 15) * STRH + (lane >> 4) * 8) * 2;
    uint32_t b_lane = (((lane & 7) + ((lane >> 4) << 3)) * STRH + ((lane >> 3) & 1) * 8) * 2;

    const __half* Ag = A + (size_t)bm * 128 * K;
    const __half* Bg = Bt + (size_t)bn * 256 * K;

    #pragma unroll
    for (int j = 0; j < GSTAGES - 1; j++) {
        uint32_t st = sb + j * (STG_H * 2);
        load_chunk(tid, st, st + A_ST_H * 2, Ag + j * KC, Bg + j * KC, K);
        cp_commit();
    }

    float acc[2][8][4];
    #pragma unroll
    for (int i = 0; i < 2; i++)
        #pragma unroll
        for (int j = 0; j < 8; j++)
            #pragma unroll
            for (int q = 0; q < 4; q++) acc[i][j][q] = 0.f;

    for (int ch = 0; ch < nch; ch++) {
        int s = ch & 3;
        uint32_t asb = sb + s * (STG_H * 2);
        uint32_t bsb = asb + A_ST_H * 2;
        cp_wait<2>();
        __syncthreads();
        if (ch + 3 < nch) {
            int sw = (ch + 3) & 3;
            uint32_t st = sb + sw * (STG_H * 2);
            load_chunk(tid, st, st + A_ST_H * 2,
                       Ag + (ch + 3) * KC, Bg + (ch + 3) * KC, K);
        }
        cp_commit();
        #pragma unroll
        for (int kk = 0; kk < 4; kk++) {
            int k = kk * 16;
            uint32_t a[2][4], b[4][4];
            #pragma unroll
            for (int i = 0; i < 2; i++)
                ldsm4(a[i], asb + a_lane + (uint32_t)(((wm * 32 + i * 16) * STRH + k) * 2));
            #pragma unroll
            for (int jp = 0; jp < 4; jp++)
                ldsm4(b[jp], bsb + b_lane + (uint32_t)(((wn * 64 + jp * 16) * STRH + k) * 2));
            #pragma unroll
            for (int i = 0; i < 2; i++)
                #pragma unroll
                for (int jp = 0; jp < 4; jp++) {
                    mma_f16(acc[i][2 * jp],     a[i], &b[jp][0]);
                    mma_f16(acc[i][2 * jp + 1], a[i], &b[jp][2]);
                }
        }
    }

    #pragma unroll
    for (int i = 0; i < 2; i++) {
        int row0 = bm * 128 + wm * 32 + i * 16 + grp;
        #pragma unroll
        for (int j = 0; j < 8; j++) {
            int col = bn * 256 + wn * 64 + j * 8 + tig * 2;
            float b0 = bias[col], b1 = bias[col + 1];
            #pragma unroll
            for (int half_ = 0; half_ < 2; half_++) {
                int row = row0 + half_ * 8;
                float v0 = acc[i][j][2 * half_]     + b0;
                float v1 = acc[i][j][2 * half_ + 1] + b1;
                if (EPI == 2) {
                    v0 = v0 > 0.f ? v0 : 0.01f * v0;
                    v1 = v1 > 0.f ? v1 : 0.01f * v1;
                }
                if (EPI == 1) {
                    float2 rv = *(const float2*)(res + (size_t)row * N + col);
                    v0 += rv.x; v1 += rv.y;
                    float2 w2; w2.x = v0; w2.y = v1;
                    *(float2*)((float*)C + (size_t)row * N + col) = w2;
                } else {
                    __half2 hw = __floats2half2_rn(v0, v1);
                    *(__half2*)((__half*)C + (size_t)row * N + col) = hw;
                }
            }
        }
    }
}

// ======================= 128x192-tile GEMM for QKV (wave-quant fix) ========
// grid = (3072/192=16, 8192/128=64) = 1024 tiles -> 6.92 waves (98.9% occ)
#define B192_ST_H (192 * STRH)
#define STG192_H (A_ST_H + B192_ST_H)          // 23040 halfs = 46080 B
#define GEMM192_SMEM (GSTAGES * STG192_H * 2)  // 184320 bytes

__device__ __forceinline__ void load_chunk192(int tid, uint32_t as, uint32_t bs,
                                              const __half* Aj, const __half* Bj, int K) {
    #pragma unroll
    for (int t = 0; t < 2; t++) {
        int v = tid + t * 512;
        int row = v >> 3, seg = v & 7;
        cpa16(as + (row * STRH + seg * 8) * 2, Aj + (size_t)row * K + seg * 8);
    }
    #pragma unroll
    for (int t = 0; t < 3; t++) {
        int v = tid + t * 512;
        int row = v >> 3, seg = v & 7;
        cpa16(bs + (row * STRH + seg * 8) * 2, Bj + (size_t)row * K + seg * 8);
    }
}

__global__ __launch_bounds__(512, 1)
void gemm_mma192(const __half* __restrict__ A, const __half* __restrict__ Bt,
                 const float* __restrict__ bias, __half* __restrict__ C,
                 int M, int N, int K) {
    extern __shared__ __half smem[];
    uint32_t sb = smem_u32(smem);
    int tid = threadIdx.x;
    int wid = tid >> 5, lane = tid & 31;
    int grp = lane >> 2, tig = lane & 3;
    int wm = wid & 3, wn = wid >> 2;          // warp tile 32x48
    int bn = blockIdx.x, bm = blockIdx.y;
    int nch = K >> 6;

    uint32_t a_lane = ((lane & 15) * STRH + (lane >> 4) * 8) * 2;
    uint32_t b_lane = (((lane & 7) + ((lane >> 4) << 3)) * STRH + ((lane >> 3) & 1) * 8) * 2;

    const __half* Ag = A + (size_t)bm * 128 * K;
    const __half* Bg = Bt + (size_t)bn * 192 * K;

    #pragma unroll
    for (int j = 0; j < GSTAGES - 1; j++) {
        uint32_t st = sb + j * (STG192_H * 2);
        load_chunk192(tid, st, st + A_ST_H * 2, Ag + j * KC, Bg + j * KC, K);
        cp_commit();
    }

    float acc[2][6][4];
    #pragma unroll
    for (int i = 0; i < 2; i++)
        #pragma unroll
        for (int j = 0; j < 6; j++)
            #pragma unroll
            for (int q = 0; q < 4; q++) acc[i][j][q] = 0.f;

    for (int ch = 0; ch < nch; ch++) {
        int s = ch & 3;
        uint32_t asb = sb + s * (STG192_H * 2);
        uint32_t bsb = asb + A_ST_H * 2;
        cp_wait<2>();
        __syncthreads();
        if (ch + 3 < nch) {
            int sw = (ch + 3) & 3;
            uint32_t st = sb + sw * (STG192_H * 2);
            load_chunk192(tid, st, st + A_ST_H * 2,
                          Ag + (ch + 3) * KC, Bg + (ch + 3) * KC, K);
        }
        cp_commit();
        #pragma unroll
        for (int kk = 0; kk < 4; kk++) {
            int k = kk * 16;
            uint32_t a[2][4], b[3][4];
            #pragma unroll
            for (int i = 0; i < 2; i++)
                ldsm4(a[i], asb + a_lane + (uint32_t)(((wm * 32 + i * 16) * STRH + k) * 2));
            #pragma unroll
            for (int jp = 0; jp < 3; jp++)
                ldsm4(b[jp], bsb + b_lane + (uint32_t)(((wn * 48 + jp * 16) * STRH + k) * 2));
            #pragma unroll
            for (int i = 0; i < 2; i++)
                #pragma unroll
                for (int jp = 0; jp < 3; jp++) {
                    mma_f16(acc[i][2 * jp],     a[i], &b[jp][0]);
                    mma_f16(acc[i][2 * jp + 1], a[i], &b[jp][2]);
                }
        }
    }

    #pragma unroll
    for (int i = 0; i < 2; i++) {
        int row0 = bm * 128 + wm * 32 + i * 16 + grp;
        #pragma unroll
        for (int j = 0; j < 6; j++) {
            int col = bn * 192 + wn * 48 + j * 8 + tig * 2;
            float b0 = bias[col], b1 = bias[col + 1];
            #pragma unroll
            for (int half_ = 0; half_ < 2; half_++) {
                int row = row0 + half_ * 8;
                float v0 = acc[i][j][2 * half_]     + b0;
                float v1 = acc[i][j][2 * half_ + 1] + b1;
                __half2 hw = __floats2half2_rn(v0, v1);
                *(__half2*)(C + (size_t)row * N + col) = hw;
            }
        }
    }
}

// ======================= fp16 tensor-core flash attention ==================
#define PST 72
#define FA_SMEM_B (512 * PST * 2)

__global__ __launch_bounds__(256)
void flash_attn_mma(const __half* __restrict__ qkv, __half* __restrict__ attn_out) {
    extern __shared__ __half fsh[];
    uint32_t sb = smem_u32(fsh);
    __half* Ps = fsh + 384 * PST;

    int tid = threadIdx.x;
    int wid = tid >> 5, lane = tid & 31;
    int grp = lane >> 2, tig = lane & 3;
    int bh = blockIdx.y;
    int b = bh >> 4, h = bh & 15;
    int q0 = blockIdx.x * 128;

    uint32_t a_lane = ((lane & 15) * PST + (lane >> 4) * 8) * 2;
    uint32_t b_lane = (((lane & 7) + ((lane >> 4) << 3)) * PST + ((lane >> 3) & 1) * 8) * 2;

    const __half* qb = qkv + (size_t)(b * SEQ + q0) * D3 + h * HS;
    const __half* kb = qkv + (size_t)(b * SEQ) * D3 + DIM + h * HS;
    const __half* vb = kb + DIM;

    #pragma unroll
    for (int t = 0; t < 4; t++) {
        int v = tid + t * 256;
        int row = v >> 3, seg = v & 7;
        cpa16(sb + (row * PST + seg * 8) * 2, qb + (size_t)row * D3 + seg * 8);
    }
    #pragma unroll
    for (int t = 0; t < 2; t++) {
        int v = tid + t * 256;
        int row = v >> 3, seg = v & 7;
        cpa16(sb + ((128 + row) * PST + seg * 8) * 2, kb + (size_t)row * D3 + seg * 8);
        cpa16(sb + ((256 + row) * PST + seg * 8) * 2, vb + (size_t)row * D3 + seg * 8);
    }
    cp_commit();

    float o[8][4];
    #pragma unroll
    for (int j = 0; j < 8; j++)
        #pragma unroll
        for (int q = 0; q < 4; q++) o[j][q] = 0.f;
    float m0 = -1e30f, m1 = -1e30f, l0 = 0.f, l1 = 0.f;

    const int NT = SEQ / 64;
    for (int kt = 0; kt < NT; kt++) {
        int pb = kt & 1, nb = pb ^ 1;
        uint32_t ks_base = sb + (128 + pb * 64) * PST * 2;
        uint32_t vs_base = sb + (256 + pb * 64) * PST * 2;
        uint32_t qs_base = sb;
        uint32_t ps_base = sb + 384 * PST * 2;

        cp_wait<0>();
        __syncthreads();

        if (kt + 1 < NT) {
            #pragma unroll
            for (int t = 0; t < 2; t++) {
                int v = tid + t * 256;
                int row = v >> 3, seg = v & 7;
                cpa16(sb + ((128 + nb * 64 + row) * PST + seg * 8) * 2,
                      kb + (size_t)((kt + 1) * 64 + row) * D3 + seg * 8);
                cpa16(sb + ((256 + nb * 64 + row) * PST + seg * 8) * 2,
                      vb + (size_t)((kt + 1) * 64 + row) * D3 + seg * 8);
            }
            cp_commit();
        }

        // ---- S = Q K^T ----
        float s[8][4];
        #pragma unroll
        for (int j = 0; j < 8; j++)
            #pragma unroll
            for (int q = 0; q < 4; q++) s[j][q] = 0.f;
        #pragma unroll
        for (int ks = 0; ks < 4; ks++) {
            int k = ks * 16;
            uint32_t a[4], bfr[4][4];
            ldsm4(a, qs_base + a_lane + (uint32_t)(((wid * 16) * PST + k) * 2));
            #pragma unroll
            for (int jp = 0; jp < 4; jp++)
                ldsm4(bfr[jp], ks_base + b_lane + (uint32_t)((jp * 16 * PST + k) * 2));
            #pragma unroll
            for (int jp = 0; jp < 4; jp++) {
                mma_f16(s[2 * jp],     a, &bfr[jp][0]);
                mma_f16(s[2 * jp + 1], a, &bfr[jp][2]);
            }
        }

        // ---- online softmax ----
        float mt0 = -1e30f, mt1 = -1e30f;
        #pragma unroll
        for (int j = 0; j < 8; j++) {
            s[j][0] *= 0.125f; s[j][1] *= 0.125f; s[j][2] *= 0.125f; s[j][3] *= 0.125f;
            mt0 = fmaxf(mt0, fmaxf(s[j][0], s[j][1]));
            mt1 = fmaxf(mt1, fmaxf(s[j][2], s[j][3]));
        }
        mt0 = fmaxf(mt0, __shfl_xor_sync(0xFFFFFFFFu, mt0, 1));
        mt0 = fmaxf(mt0, __shfl_xor_sync(0xFFFFFFFFu, mt0, 2));
        mt1 = fmaxf(mt1, __shfl_xor_sync(0xFFFFFFFFu, mt1, 1));
        mt1 = fmaxf(mt1, __shfl_xor_sync(0xFFFFFFFFu, mt1, 2));
        float mn0 = fmaxf(m0, mt0), mn1 = fmaxf(m1, mt1);
        float al0 = __expf(m0 - mn0), al1 = __expf(m1 - mn1);
        float lt0 = 0.f, lt1 = 0.f;
        #pragma unroll
        for (int j = 0; j < 8; j++) {
            s[j][0] = __expf(s[j][0] - mn0); s[j][1] = __expf(s[j][1] - mn0);
            s[j][2] = __expf(s[j][2] - mn1); s[j][3] = __expf(s[j][3] - mn1);
            lt0 += s[j][0] + s[j][1];
            lt1 += s[j][2] + s[j][3];
        }
        lt0 += __shfl_xor_sync(0xFFFFFFFFu, lt0, 1);
        lt0 += __shfl_xor_sync(0xFFFFFFFFu, lt0, 2);
        lt1 += __shfl_xor_sync(0xFFFFFFFFu, lt1, 1);
        lt1 += __shfl_xor_sync(0xFFFFFFFFu, lt1, 2);
        m0 = mn0; m1 = mn1;
        l0 = l0 * al0 + lt0;
        l1 = l1 * al1 + lt1;
        #pragma unroll
        for (int j = 0; j < 8; j++) {
            o[j][0] *= al0; o[j][1] *= al0; o[j][2] *= al1; o[j][3] *= al1;
        }
        #pragma unroll
        for (int j = 0; j < 8; j++) {
            *(__half2*)(Ps + (wid * 16 + grp) * PST + j * 8 + 2 * tig) =
                __floats2half2_rn(s[j][0], s[j][1]);
            *(__half2*)(Ps + (wid * 16 + grp + 8) * PST + j * 8 + 2 * tig) =
                __floats2half2_rn(s[j][2], s[j][3]);
        }
        __syncwarp();

        // ---- O += P V ----
        #pragma unroll
        for (int ks = 0; ks < 4; ks++) {
            int k = ks * 16;
            uint32_t a[4], bfr[4][4];
            ldsm4(a, ps_base + a_lane + (uint32_t)(((wid * 16) * PST + k) * 2));
            #pragma unroll
            for (int jp = 0; jp < 4; jp++)
                ldsm4t(bfr[jp], vs_base + a_lane + (uint32_t)((k * PST + jp * 16) * 2));
            #pragma unroll
            for (int jp = 0; jp < 4; jp++) {
                mma_f16(o[2 * jp],     a, &bfr[jp][0]);
                mma_f16(o[2 * jp + 1], a, &bfr[jp][2]);
            }
        }
    }

    // ---- epilogue ----
    float inv0 = 1.0f / l0, inv1 = 1.0f / l1;
    size_t r0 = (size_t)(b * SEQ + q0 + wid * 16 + grp);
    #pragma unroll
    for (int j = 0; j < 8; j++) {
        int col = h * HS + j * 8 + tig * 2;
        *(__half2*)(attn_out + r0 * DIM + col) =
            __floats2half2_rn(o[j][0] * inv0, o[j][1] * inv0);
        *(__half2*)(attn_out + (r0 + 8) * DIM + col) =
            __floats2half2_rn(o[j][2] * inv1, o[j][3] * inv1);
    }
}

// ---------------- host orchestration ---------------------------------------
extern "C" void kernel_launch(void* const* d_in, const int* in_sizes, int n_in,
                              void* d_out, int out_size) {
    const float* x     = (const float*)d_in[0];
    const float* Wq    = (const float*)d_in[1];
    const float* bq    = (const float*)d_in[2];
    const float* Wk    = (const float*)d_in[3];
    const float* bk    = (const float*)d_in[4];
    const float* Wv    = (const float*)d_in[5];
    const float* bv    = (const float*)d_in[6];
    const float* Wproj = (const float*)d_in[7];
    const float* bproj = (const float*)d_in[8];
    const float* W1    = (const float*)d_in[9];
    const float* b1    = (const float*)d_in[10];
    const float* W2    = (const float*)d_in[11];
    const float* b2    = (const float*)d_in[12];
    const float* ln1_g = (const float*)d_in[13];
    const float* ln1_b = (const float*)d_in[14];
    const float* ln2_g = (const float*)d_in[15];
    const float* ln2_b = (const float*)d_in[16];
    float* out = (float*)d_out;

    __half *h, *qkv, *attn, *ff, *wqkvT, *wprojT, *w1T, *w2T;
    float *x1, *bqkv;
    cudaGetSymbolAddress((void**)&h,      g_h);
    cudaGetSymbolAddress((void**)&qkv,    g_qkv);
    cudaGetSymbolAddress((void**)&attn,   g_attn);
    cudaGetSymbolAddress((void**)&x1,     g_x1);
    cudaGetSymbolAddress((void**)&ff,     g_ff);
    cudaGetSymbolAddress((void**)&wqkvT,  g_wqkvT);
    cudaGetSymbolAddress((void**)&wprojT, g_wprojT);
    cudaGetSymbolAddress((void**)&w1T,    g_w1T);
    cudaGetSymbolAddress((void**)&w2T,    g_w2T);
    cudaGetSymbolAddress((void**)&bqkv,   g_bqkv);

    cudaFuncSetAttribute(flash_attn_mma, cudaFuncAttributeMaxDynamicSharedMemorySize, FA_SMEM_B);
    cudaFuncSetAttribute(gemm_mma<1>, cudaFuncAttributeMaxDynamicSharedMemorySize, GEMM_SMEM);
    cudaFuncSetAttribute(gemm_mma<2>, cudaFuncAttributeMaxDynamicSharedMemorySize, GEMM_SMEM);
    cudaFuncSetAttribute(gemm_mma192, cudaFuncAttributeMaxDynamicSharedMemorySize, GEMM192_SMEM);

    dim3 tb(32, 8);
    // launch 0
    prep_qkv<<<dim3(HS/32, DIM/32, NH), tb>>>(Wq, Wk, Wv, bq, bk, bv);
    // launch 1
    prep_w<<<dim3(128, 128, 3), tb>>>(Wproj, W1, W2);
    // launch 2
    ln_kernel<<<TOK/2, 256>>>(x, ln1_g, ln1_b, h);
    // launch 3: QKV with 128x192 tiles (1024 tiles -> 98.9% wave occupancy)
    gemm_mma192<<<dim3(D3/192, TOK/128), 512, GEMM192_SMEM>>>(h, wqkvT, bqkv, qkv, TOK, D3, DIM);
    // launch 4
    flash_attn_mma<<<dim3(SEQ/128, BATCH*NH), 256, FA_SMEM_B>>>(qkv, attn);
    // launch 5
    gemm_mma<1><<<dim3(DIM/256, TOK/128), 512, GEMM_SMEM>>>(attn, wprojT, bproj, x, x1, TOK, DIM, DIM);
    // launch 6
    ln_kernel<<<TOK/2, 256>>>(x1, ln2_g, ln2_b, h);
    // launch 7
    gemm_mma<2><<<dim3(FFD/256, TOK/128), 512, GEMM_SMEM>>>(h, w1T, b1, nullptr, ff, TOK, FFD, DIM);
    // launch 8
    gemm_mma<1><<<dim3(DIM/256, TOK/128), 512, GEMM_SMEM>>>(ff, w2T, b2, x1, out, TOK, DIM, FFD);
}